// round 1
// baseline (speedup 1.0000x reference)
#include <cuda_runtime.h>
#include <math.h>

#define D 512
#define V 17

// Scratch (allocation-free): intermediate gelu(E@W1+b1) and final per-vocab hidden H.
__device__ float g_mid[V * D];
__device__ float g_H[V * D];

// ---------------------------------------------------------------------------
// Kernel 1: g_mid[v][j] = gelu(sum_k E[v][k] * W1[k][j] + b1[j])
// grid (V, D/256), block 256. W1 reads coalesced; E row broadcast from smem.
// ---------------------------------------------------------------------------
__global__ void k_mid(const float* __restrict__ E,
                      const float* __restrict__ W1,
                      const float* __restrict__ b1) {
    const int v = blockIdx.x;
    const int j = blockIdx.y * blockDim.x + threadIdx.x;

    __shared__ float e[D];
    for (int k = threadIdx.x; k < D; k += blockDim.x) e[k] = E[v * D + k];
    __syncthreads();

    float acc = b1[j];
#pragma unroll 8
    for (int k = 0; k < D; k++) acc += e[k] * W1[k * D + j];

    // exact GELU: 0.5*x*(1+erf(x/sqrt(2)))
    const float x = acc;
    g_mid[v * D + j] = 0.5f * x * (1.0f + erff(x * 0.70710678118654752f));
}

// ---------------------------------------------------------------------------
// Kernel 2: g_H[v][j] = sum_k g_mid[v][k] * W2[k][j] + b2[j]
// ---------------------------------------------------------------------------
__global__ void k_hid(const float* __restrict__ W2,
                      const float* __restrict__ b2) {
    const int v = blockIdx.x;
    const int j = blockIdx.y * blockDim.x + threadIdx.x;

    __shared__ float m[D];
    for (int k = threadIdx.x; k < D; k += blockDim.x) m[k] = g_mid[v * D + k];
    __syncthreads();

    float acc = b2[j];
#pragma unroll 8
    for (int k = 0; k < D; k++) acc += m[k] * W2[k * D + j];

    g_H[v * D + j] = acc;
}

// ---------------------------------------------------------------------------
// Kernel 3: per-segment histogram over 17 vocab bins, then
//   out[s][j] = (sum_v cnt[v] * H[v][j]) / seg_len
// One CTA per segment, 512 threads (=16 warps). Per-warp private histograms
// in shared memory to avoid same-bin atomic serialization.
// ---------------------------------------------------------------------------
__global__ void k_seg(const int* __restrict__ tok,
                      const int* __restrict__ cu,
                      float* __restrict__ out) {
    const int s = blockIdx.x;
    const int start = cu[s];
    const int end = cu[s + 1];
    const int tid = threadIdx.x;
    const int wid = tid >> 5;

    __shared__ int cnt[16][V + 3];   // pad to 20 ints/row: stride co-prime-ish w/ banks
    __shared__ float fc[V];

    for (int i = tid; i < 16 * (V + 3); i += blockDim.x)
        (&cnt[0][0])[i] = 0;
    __syncthreads();

    for (int i = start + tid; i < end; i += blockDim.x) {
        atomicAdd(&cnt[wid][tok[i]], 1);
    }
    __syncthreads();

    if (tid < V) {
        int c = 0;
#pragma unroll
        for (int w = 0; w < 16; w++) c += cnt[w][tid];
        fc[tid] = (float)c;
    }
    __syncthreads();

    const float inv = 1.0f / (float)(end - start);
    const int j = tid;               // blockDim.x == D == 512
    float acc = 0.0f;
#pragma unroll
    for (int v = 0; v < V; v++) acc += fc[v] * g_H[v * D + j];
    out[s * D + j] = acc * inv;
}

// ---------------------------------------------------------------------------
// Inputs (metadata order): packed_tokens[T] i32, cu_seq_lens[S+1] i32,
// embedding[17*512] f32, W1[512*512] f32, b1[512] f32, W2[512*512] f32,
// b2[512] f32. Output: [S, 512] f32.
// ---------------------------------------------------------------------------
extern "C" void kernel_launch(void* const* d_in, const int* in_sizes, int n_in,
                              void* d_out, int out_size) {
    const int*   tok = (const int*)  d_in[0];
    const int*   cu  = (const int*)  d_in[1];
    const float* E   = (const float*)d_in[2];
    const float* W1  = (const float*)d_in[3];
    const float* b1  = (const float*)d_in[4];
    const float* W2  = (const float*)d_in[5];
    const float* b2  = (const float*)d_in[6];
    float*       out = (float*)d_out;

    const int n_segs = in_sizes[1] - 1;

    dim3 g1(V, D / 256);
    k_mid<<<g1, 256>>>(E, W1, b1);
    k_hid<<<g1, 256>>>(W2, b2);
    k_seg<<<n_segs, D>>>(tok, cu, out);
}

// round 2
// speedup vs baseline: 1.6383x; 1.6383x over previous
#include <cuda_runtime.h>
#include <math.h>

#define D 512
#define V 17
#define MAX_SEGS 128
#define NSUB 4          // histogram sub-chunks per segment

// Scratch (allocation-free, graph-safe).
__device__ float g_mid[V * D];               // gelu(E@W1+b1)
__device__ float g_H[V * D];                 // g_mid@W2+b2
__device__ int   g_cnt[MAX_SEGS * NSUB * V]; // partial histograms

// Shared scratch union: full E/mid table, reduction buffer, or histogram.
union SmemU {
    float e[V * D];            // 34816 B
    float red[16 * V * 32];    // 34816 B
    int   cnt[16 * 32];        // tiny
};

// ---------------------------------------------------------------------------
// GEMM tile body: out 17 x 512 = A(17x512) @ W(512x512) (+bias, optional gelu)
// CTA covers 32 j-columns; 512 threads = 32 (j) x 16 (k-slices of 32).
// Each W element is loaded once, reused across all 17 rows of A (in smem).
// ---------------------------------------------------------------------------
__device__ __forceinline__ void gemm_tile(SmemU& sm,
                                          const float* __restrict__ A,
                                          const float* __restrict__ W,
                                          const float* __restrict__ bias,
                                          float* __restrict__ outp,
                                          int jtile, bool do_gelu) {
    const int tid = threadIdx.x;
    const int tx = tid & 31;      // j within tile
    const int ty = tid >> 5;      // k-slice (warp id)
    const int j = jtile * 32 + tx;

    // stage A (17x512) into smem
    for (int i = tid; i < V * D; i += 512) sm.e[i] = A[i];
    __syncthreads();

    float acc[V];
#pragma unroll
    for (int v = 0; v < V; v++) acc[v] = 0.0f;

    const int k0 = ty * 32;
#pragma unroll 4
    for (int kk = 0; kk < 32; kk++) {
        const float w = W[(k0 + kk) * D + j];
#pragma unroll
        for (int v = 0; v < V; v++) acc[v] += sm.e[v * D + k0 + kk] * w;
    }
    __syncthreads();           // done reading sm.e; reuse as reduction buffer

#pragma unroll
    for (int v = 0; v < V; v++) sm.red[(ty * V + v) * 32 + tx] = acc[v];
    __syncthreads();

    // 17*32 = 544 outputs; 512 threads loop (<=2 iters)
    for (int o = tid; o < V * 32; o += 512) {
        const int v = o >> 5;
        const int t = o & 31;
        float s = 0.0f;
#pragma unroll
        for (int sl = 0; sl < 16; sl++) s += sm.red[(sl * V + v) * 32 + t];
        s += bias[jtile * 32 + t];
        if (do_gelu)
            s = 0.5f * s * (1.0f + erff(s * 0.70710678118654752f));
        outp[v * D + jtile * 32 + t] = s;
    }
}

// ---------------------------------------------------------------------------
// Kernel 1: CTAs 0..15 compute g_mid = gelu(E@W1+b1).
//           CTAs 16..16+NSUB*n_segs-1 compute partial token histograms.
// ---------------------------------------------------------------------------
__global__ void __launch_bounds__(512, 1)
k1(const float* __restrict__ E, const float* __restrict__ W1,
   const float* __restrict__ b1, const int* __restrict__ tok,
   const int* __restrict__ cu, int n_segs) {
    __shared__ SmemU sm;
    const int bid = blockIdx.x;
    const int tid = threadIdx.x;

    if (bid < 16) {
        gemm_tile(sm, E, W1, b1, g_mid, bid, true);
        return;
    }

    // histogram CTA
    const int h = bid - 16;
    const int s = h >> 2;            // NSUB == 4
    const int sub = h & 3;
    if (s >= n_segs) return;

    const int start = cu[s];
    const int end = cu[s + 1];
    const int len = end - start;
    const int q = (len + NSUB - 1) >> 2;
    const int lo = start + sub * q;
    const int hi = min(lo + q, end);
    const int wid = tid >> 5;

    for (int i = tid; i < 16 * 32; i += 512) sm.cnt[i] = 0;
    __syncthreads();

    for (int i = lo + tid; i < hi; i += 512)
        atomicAdd(&sm.cnt[wid * 32 + tok[i]], 1);
    __syncthreads();

    if (tid < V) {
        int c = 0;
#pragma unroll
        for (int w = 0; w < 16; w++) c += sm.cnt[w * 32 + tid];
        g_cnt[(s * NSUB + sub) * V + tid] = c;
    }
}

// ---------------------------------------------------------------------------
// Kernel 2: g_H = g_mid @ W2 + b2   (16 CTAs)
// ---------------------------------------------------------------------------
__global__ void __launch_bounds__(512, 1)
k2(const float* __restrict__ W2, const float* __restrict__ b2) {
    __shared__ SmemU sm;
    gemm_tile(sm, g_mid, W2, b2, g_H, blockIdx.x, false);
}

// ---------------------------------------------------------------------------
// Kernel 3: out[s][j] = (sum_v cnt[s][v] * H[v][j]) / len_s   (n_segs CTAs)
// ---------------------------------------------------------------------------
__global__ void __launch_bounds__(512, 1)
k3(const int* __restrict__ cu, float* __restrict__ out) {
    const int s = blockIdx.x;
    const int tid = threadIdx.x;
    __shared__ float fc[V];

    if (tid < V) {
        int c = 0;
#pragma unroll
        for (int u = 0; u < NSUB; u++) c += g_cnt[(s * NSUB + u) * V + tid];
        fc[tid] = (float)c;
    }
    __syncthreads();

    const float inv = 1.0f / (float)(cu[s + 1] - cu[s]);
    float acc = 0.0f;
#pragma unroll
    for (int v = 0; v < V; v++) acc += fc[v] * g_H[v * D + tid];
    out[s * D + tid] = acc * inv;
}

// ---------------------------------------------------------------------------
extern "C" void kernel_launch(void* const* d_in, const int* in_sizes, int n_in,
                              void* d_out, int out_size) {
    const int*   tok = (const int*)  d_in[0];
    const int*   cu  = (const int*)  d_in[1];
    const float* E   = (const float*)d_in[2];
    const float* W1  = (const float*)d_in[3];
    const float* b1  = (const float*)d_in[4];
    const float* W2  = (const float*)d_in[5];
    const float* b2  = (const float*)d_in[6];
    float*       out = (float*)d_out;

    int n_segs = in_sizes[1] - 1;
    if (n_segs > MAX_SEGS) n_segs = MAX_SEGS;

    k1<<<16 + NSUB * n_segs, 512>>>(E, W1, b1, tok, cu, n_segs);
    k2<<<16, 512>>>(W2, b2);
    k3<<<n_segs, 512>>>(cu, out);
}